// round 3
// baseline (speedup 1.0000x reference)
#include <cuda_runtime.h>
#include <math.h>

#define BATCH 4
#define NTOK 4096      // H*W tokens
#define CDIM 512
#define NGROUP 32
#define GSZ (CDIM / NGROUP)   // 16 channels per group
#define GELEMS (NTOK * GSZ)   // 65536 elements per (b,g) group

// ---------------- scratch (static device memory; no allocations) ----------------
__device__ float g_h[(size_t)BATCH * NTOK * CDIM];
__device__ float g_q[(size_t)BATCH * NTOK * CDIM];
__device__ float g_k[(size_t)BATCH * NTOK * CDIM];
__device__ float g_v[(size_t)BATCH * NTOK * CDIM];
__device__ float g_o[(size_t)BATCH * NTOK * CDIM];
__device__ float g_s[(size_t)BATCH * NTOK * NTOK];   // 256 MB attention scores
__device__ float g_mean[BATCH * NGROUP];
__device__ float g_rstd[BATCH * NGROUP];

// ---------------- GroupNorm: per-(b,g) mean / rstd ----------------
__global__ __launch_bounds__(512) void gn_stats(const float* __restrict__ x,
                                                float* __restrict__ mean,
                                                float* __restrict__ rstd) {
    int bg = blockIdx.x;            // 0..127
    int b = bg >> 5, g = bg & 31;
    const float* base = x + (size_t)b * NTOK * CDIM + g * GSZ;
    float s = 0.f, ss = 0.f;
    // 65536 elems per group = 16384 float4s
    for (int l = threadIdx.x; l < NTOK * 4; l += 512) {
        int n = l >> 2;
        int j = (l & 3) * 4;
        float4 t = *(const float4*)(base + (size_t)n * CDIM + j);
        s  += t.x + t.y + t.z + t.w;
        ss += t.x * t.x + t.y * t.y + t.z * t.z + t.w * t.w;
    }
    __shared__ float rs_[512];
    __shared__ float rss[512];
    rs_[threadIdx.x] = s;
    rss[threadIdx.x] = ss;
    __syncthreads();
    for (int st = 256; st > 0; st >>= 1) {
        if (threadIdx.x < st) {
            rs_[threadIdx.x] += rs_[threadIdx.x + st];
            rss[threadIdx.x] += rss[threadIdx.x + st];
        }
        __syncthreads();
    }
    if (threadIdx.x == 0) {
        float mu  = rs_[0] * (1.f / (float)GELEMS);
        float var = rss[0] * (1.f / (float)GELEMS) - mu * mu;
        mean[bg] = mu;
        rstd[bg] = rsqrtf(var + 1e-6f);
    }
}

__global__ __launch_bounds__(256) void gn_apply(const float* __restrict__ x,
                                                const float* __restrict__ mean,
                                                const float* __restrict__ rstd,
                                                const float* __restrict__ gamma,
                                                const float* __restrict__ beta,
                                                float* __restrict__ h) {
    size_t i = (size_t)blockIdx.x * blockDim.x + threadIdx.x;  // float4 index
    size_t e = i * 4;
    int c = (int)(e & (CDIM - 1));
    size_t bn = e >> 9;            // b*NTOK + n
    int b = (int)(bn >> 12);
    int g = c >> 4;
    int bg = b * NGROUP + g;
    float mu = mean[bg], rs = rstd[bg];
    float4 xv = *(const float4*)(x + e);
    float4 gv = *(const float4*)(gamma + c);
    float4 bv = *(const float4*)(beta + c);
    float4 o;
    o.x = (xv.x - mu) * rs * gv.x + bv.x;
    o.y = (xv.y - mu) * rs * gv.y + bv.y;
    o.z = (xv.z - mu) * rs * gv.z + bv.z;
    o.w = (xv.w - mu) * rs * gv.w + bv.w;
    *(float4*)(h + e) = o;
}

// ---------------- 128x128x8 register-blocked SGEMM ----------------
// C[M,N] = alpha * A[M,K] @ op(B) (+ bias[N]) (+ resid[M,N])
// TRANSB=false: B is [K,N] row-major (NN).  TRANSB=true: B is [N,K] row-major (NT).
// All of M,N divisible by 128, K divisible by 8 for every call in this problem.
template <bool TRANSB>
__global__ __launch_bounds__(256) void gemm128(
    const float* __restrict__ A, const float* __restrict__ Bm,
    const float* __restrict__ bias, const float* __restrict__ resid,
    float* __restrict__ Cm, int M, int N, int K, float alpha,
    size_t sA, size_t sB, size_t sC) {
    __shared__ float As[8][128];
    __shared__ float Bs[8][128];

    A  += (size_t)blockIdx.z * sA;
    Bm += (size_t)blockIdx.z * sB;
    Cm += (size_t)blockIdx.z * sC;
    const float* R = resid ? (resid + (size_t)blockIdx.z * sC) : nullptr;

    const int tid = threadIdx.x;
    const int bm = blockIdx.y * 128;
    const int bn = blockIdx.x * 128;
    const int arow = tid >> 1;
    const int acol = (tid & 1) * 4;
    const int brow = tid >> 5;
    const int bcol = (tid & 31) * 4;
    const int ty = tid >> 4, tx = tid & 15;

    float acc[8][8];
#pragma unroll
    for (int i = 0; i < 8; i++)
#pragma unroll
        for (int j = 0; j < 8; j++) acc[i][j] = 0.f;

    for (int k0 = 0; k0 < K; k0 += 8) {
        float4 av = *(const float4*)(A + (size_t)(bm + arow) * K + (k0 + acol));
        As[acol + 0][arow] = av.x;
        As[acol + 1][arow] = av.y;
        As[acol + 2][arow] = av.z;
        As[acol + 3][arow] = av.w;
        if (TRANSB) {
            float4 bv = *(const float4*)(Bm + (size_t)(bn + arow) * K + (k0 + acol));
            Bs[acol + 0][arow] = bv.x;
            Bs[acol + 1][arow] = bv.y;
            Bs[acol + 2][arow] = bv.z;
            Bs[acol + 3][arow] = bv.w;
        } else {
            *(float4*)&Bs[brow][bcol] =
                *(const float4*)(Bm + (size_t)(k0 + brow) * N + (bn + bcol));
        }
        __syncthreads();
#pragma unroll
        for (int k = 0; k < 8; k++) {
            float ra[8], rb[8];
            *(float4*)&ra[0] = *(const float4*)&As[k][ty * 8];
            *(float4*)&ra[4] = *(const float4*)&As[k][ty * 8 + 4];
            *(float4*)&rb[0] = *(const float4*)&Bs[k][tx * 8];
            *(float4*)&rb[4] = *(const float4*)&Bs[k][tx * 8 + 4];
#pragma unroll
            for (int i = 0; i < 8; i++)
#pragma unroll
                for (int j = 0; j < 8; j++) acc[i][j] += ra[i] * rb[j];
        }
        __syncthreads();
    }

#pragma unroll
    for (int i = 0; i < 8; i++) {
        int row = bm + ty * 8 + i;
#pragma unroll
        for (int j0 = 0; j0 < 8; j0 += 4) {
            int col = bn + tx * 8 + j0;
            float4 o;
            o.x = acc[i][j0 + 0] * alpha;
            o.y = acc[i][j0 + 1] * alpha;
            o.z = acc[i][j0 + 2] * alpha;
            o.w = acc[i][j0 + 3] * alpha;
            if (bias) {
                float4 bb = *(const float4*)(bias + col);
                o.x += bb.x; o.y += bb.y; o.z += bb.z; o.w += bb.w;
            }
            if (R) {
                float4 rv = *(const float4*)(R + (size_t)row * N + col);
                o.x += rv.x; o.y += rv.y; o.z += rv.z; o.w += rv.w;
            }
            *(float4*)(Cm + (size_t)row * N + col) = o;
        }
    }
}

// ---------------- row softmax, row length 4096 ----------------
__global__ __launch_bounds__(256) void softmax4096(float* __restrict__ S) {
    float4* p = (float4*)(S + (size_t)blockIdx.x * NTOK);
    int tid = threadIdx.x;
    float4 v[4];
    float m = -1e30f;
#pragma unroll
    for (int i = 0; i < 4; i++) {
        v[i] = p[tid + i * 256];
        m = fmaxf(m, fmaxf(fmaxf(v[i].x, v[i].y), fmaxf(v[i].z, v[i].w)));
    }
    __shared__ float red[256];
    red[tid] = m;
    __syncthreads();
    for (int s = 128; s > 0; s >>= 1) {
        if (tid < s) red[tid] = fmaxf(red[tid], red[tid + s]);
        __syncthreads();
    }
    m = red[0];
    __syncthreads();
    float sum = 0.f;
#pragma unroll
    for (int i = 0; i < 4; i++) {
        v[i].x = __expf(v[i].x - m);
        v[i].y = __expf(v[i].y - m);
        v[i].z = __expf(v[i].z - m);
        v[i].w = __expf(v[i].w - m);
        sum += v[i].x + v[i].y + v[i].z + v[i].w;
    }
    red[tid] = sum;
    __syncthreads();
    for (int s = 128; s > 0; s >>= 1) {
        if (tid < s) red[tid] += red[tid + s];
        __syncthreads();
    }
    float inv = 1.f / red[0];
#pragma unroll
    for (int i = 0; i < 4; i++) {
        v[i].x *= inv; v[i].y *= inv; v[i].z *= inv; v[i].w *= inv;
        p[tid + i * 256] = v[i];
    }
}

// ---------------- launch ----------------
extern "C" void kernel_launch(void* const* d_in, const int* in_sizes, int n_in,
                              void* d_out, int out_size) {
    const float* x     = (const float*)d_in[0];
    const float* gamma = (const float*)d_in[1];
    const float* beta  = (const float*)d_in[2];
    const float* Wq    = (const float*)d_in[3];
    const float* bq    = (const float*)d_in[4];
    const float* Wk    = (const float*)d_in[5];
    const float* bk    = (const float*)d_in[6];
    const float* Wv    = (const float*)d_in[7];
    const float* bv    = (const float*)d_in[8];
    const float* Wo    = (const float*)d_in[9];
    const float* bo    = (const float*)d_in[10];
    float* out = (float*)d_out;

    float *h, *q, *kk, *v, *o, *s, *mean, *rstd;
    cudaGetSymbolAddress((void**)&h, g_h);
    cudaGetSymbolAddress((void**)&q, g_q);
    cudaGetSymbolAddress((void**)&kk, g_k);
    cudaGetSymbolAddress((void**)&v, g_v);
    cudaGetSymbolAddress((void**)&o, g_o);
    cudaGetSymbolAddress((void**)&s, g_s);
    cudaGetSymbolAddress((void**)&mean, g_mean);
    cudaGetSymbolAddress((void**)&rstd, g_rstd);

    const size_t NC = (size_t)NTOK * CDIM;
    const size_t NN = (size_t)NTOK * NTOK;
    const int MTOT = BATCH * NTOK;                 // 16384
    const float inv_sqrt_c = 0.044194173824159216f; // 1/sqrt(512)

    // 1) GroupNorm
    gn_stats<<<BATCH * NGROUP, 512>>>(x, mean, rstd);
    gn_apply<<<(MTOT * CDIM / 4) / 256, 256>>>(x, mean, rstd, gamma, beta, h);

    // 2) Q, K, V projections: [16384,512] @ [512,512] + bias
    dim3 blk(256);
    dim3 gProj(CDIM / 128, MTOT / 128, 1);
    gemm128<false><<<gProj, blk>>>(h, Wq, bq, nullptr, q, MTOT, CDIM, CDIM, 1.f, 0, 0, 0);
    gemm128<false><<<gProj, blk>>>(h, Wk, bk, nullptr, kk, MTOT, CDIM, CDIM, 1.f, 0, 0, 0);
    gemm128<false><<<gProj, blk>>>(h, Wv, bv, nullptr, v, MTOT, CDIM, CDIM, 1.f, 0, 0, 0);

    // 3) scores = q @ k^T * (1/sqrt(C)), batched NT
    dim3 gScore(NTOK / 128, NTOK / 128, BATCH);
    gemm128<true><<<gScore, blk>>>(q, kk, nullptr, nullptr, s,
                                   NTOK, NTOK, CDIM, inv_sqrt_c, NC, NC, NN);

    // 4) softmax over each of 16384 rows
    softmax4096<<<BATCH * NTOK, 256>>>(s);

    // 5) out = attn @ v, batched NN
    dim3 gPV(CDIM / 128, NTOK / 128, BATCH);
    gemm128<false><<<gPV, blk>>>(s, v, nullptr, nullptr, o,
                                 NTOK, CDIM, NTOK, 1.f, NN, NC, NC);

    // 6) final projection + bias + residual
    gemm128<false><<<gProj, blk>>>(o, Wo, bo, x, out, MTOT, CDIM, CDIM, 1.f, 0, 0, 0);
}

// round 8
// speedup vs baseline: 2.8452x; 2.8452x over previous
#include <cuda_runtime.h>
#include <math.h>
#include <stdint.h>

#define BATCH 4
#define NTOK 4096      // H*W tokens
#define CDIM 512
#define NGROUP 32
#define GSZ (CDIM / NGROUP)   // 16 channels per group
#define GELEMS (NTOK * GSZ)   // 65536 elements per (b,g) group

// ---------------- scratch (static device memory; no allocations) ----------------
__device__ float g_h[(size_t)BATCH * NTOK * CDIM];
__device__ float g_q[(size_t)BATCH * NTOK * CDIM];
__device__ float g_k[(size_t)BATCH * NTOK * CDIM];
__device__ float g_v[(size_t)BATCH * NTOK * CDIM];
__device__ float g_o[(size_t)BATCH * NTOK * CDIM];
__device__ float g_s[(size_t)BATCH * NTOK * NTOK];   // 256 MB attention scores
__device__ float g_mean[BATCH * NGROUP];
__device__ float g_rstd[BATCH * NGROUP];

// ---------------- GroupNorm: per-(b,g) mean / rstd ----------------
__global__ __launch_bounds__(512) void gn_stats(const float* __restrict__ x,
                                                float* __restrict__ mean,
                                                float* __restrict__ rstd) {
    int bg = blockIdx.x;            // 0..127
    int b = bg >> 5, g = bg & 31;
    const float* base = x + (size_t)b * NTOK * CDIM + g * GSZ;
    float s = 0.f, ss = 0.f;
    for (int l = threadIdx.x; l < NTOK * 4; l += 512) {
        int n = l >> 2;
        int j = (l & 3) * 4;
        float4 t = *(const float4*)(base + (size_t)n * CDIM + j);
        s  += t.x + t.y + t.z + t.w;
        ss += t.x * t.x + t.y * t.y + t.z * t.z + t.w * t.w;
    }
    __shared__ float rs_[512];
    __shared__ float rss[512];
    rs_[threadIdx.x] = s;
    rss[threadIdx.x] = ss;
    __syncthreads();
    for (int st = 256; st > 0; st >>= 1) {
        if (threadIdx.x < st) {
            rs_[threadIdx.x] += rs_[threadIdx.x + st];
            rss[threadIdx.x] += rss[threadIdx.x + st];
        }
        __syncthreads();
    }
    if (threadIdx.x == 0) {
        float mu  = rs_[0] * (1.f / (float)GELEMS);
        float var = rss[0] * (1.f / (float)GELEMS) - mu * mu;
        mean[bg] = mu;
        rstd[bg] = rsqrtf(var + 1e-6f);
    }
}

__global__ __launch_bounds__(256) void gn_apply(const float* __restrict__ x,
                                                const float* __restrict__ mean,
                                                const float* __restrict__ rstd,
                                                const float* __restrict__ gamma,
                                                const float* __restrict__ beta,
                                                float* __restrict__ h) {
    size_t i = (size_t)blockIdx.x * blockDim.x + threadIdx.x;  // float4 index
    size_t e = i * 4;
    int c = (int)(e & (CDIM - 1));
    size_t bn = e >> 9;            // b*NTOK + n
    int b = (int)(bn >> 12);
    int g = c >> 4;
    int bg = b * NGROUP + g;
    float mu = mean[bg], rs = rstd[bg];
    float4 xv = *(const float4*)(x + e);
    float4 gv = *(const float4*)(gamma + c);
    float4 bv = *(const float4*)(beta + c);
    float4 o;
    o.x = (xv.x - mu) * rs * gv.x + bv.x;
    o.y = (xv.y - mu) * rs * gv.y + bv.y;
    o.z = (xv.z - mu) * rs * gv.z + bv.z;
    o.w = (xv.w - mu) * rs * gv.w + bv.w;
    *(float4*)(h + e) = o;
}

// ---------------- TF32 tensor-core GEMM, cp.async double-buffered ----------------
// C[M,N] = alpha * A[M,K] @ op(B) (+ bias[N]) (+ resid[M,N])
// TRANSB=false: B is [K,N] row-major (NN).  TRANSB=true: B is [N,K] row-major (NT).
// Block tile 128x128, kTile 16, 256 threads = 8 warps (2 along M x 4 along N),
// warp tile 64x32 from m16n8k8 tf32 MMAs, fp32 accumulate.
// Smem holds raw fp32 (cp.async); cvt.rna.tf32 applied after LDS.

__device__ __forceinline__ uint32_t f2tf(float f) {
    uint32_t u;
    asm("cvt.rna.tf32.f32 %0, %1;" : "=r"(u) : "f"(f));
    return u;
}

__device__ __forceinline__ void cpasync16(uint32_t dst_smem, const float* src) {
    asm volatile("cp.async.cg.shared.global [%0], [%1], 16;\n"
                 :: "r"(dst_smem), "l"(src));
}

__device__ __forceinline__ void mma_tf32(float* c, const uint32_t* a, const uint32_t* b) {
    asm volatile(
        "mma.sync.aligned.m16n8k8.row.col.f32.tf32.tf32.f32 "
        "{%0,%1,%2,%3}, {%4,%5,%6,%7}, {%8,%9}, {%0,%1,%2,%3};\n"
        : "+f"(c[0]), "+f"(c[1]), "+f"(c[2]), "+f"(c[3])
        : "r"(a[0]), "r"(a[1]), "r"(a[2]), "r"(a[3]), "r"(b[0]), "r"(b[1]));
}

template <bool TRANSB>
__global__ __launch_bounds__(256) void gemm_tf32(
    const float* __restrict__ A, const float* __restrict__ Bm,
    const float* __restrict__ bias, const float* __restrict__ resid,
    float* __restrict__ Cm, int M, int N, int K, float alpha,
    size_t sA, size_t sB, size_t sC) {
    // As[m][20] per buffer: fragment bank = (20*gp + tg) % 32, bijective (conflict-free).
    // TRANSB:  Bs[n][20]  (same property).
    // !TRANSB: Bs[k][136]: fragment bank = (8*tg + gp) % 32, bijective.
    constexpr int PA = 20;
    constexpr int PBN = 136;
    constexpr int ASZ = 128 * PA;                       // 2560 floats / buffer
    constexpr int BSZ = TRANSB ? 128 * PA : 16 * PBN;   // per buffer
    __shared__ float As[2 * ASZ];
    __shared__ float Bs[2 * BSZ];

    A  += (size_t)blockIdx.z * sA;
    Bm += (size_t)blockIdx.z * sB;
    Cm += (size_t)blockIdx.z * sC;
    const float* R = resid ? (resid + (size_t)blockIdx.z * sC) : nullptr;

    const int tid = threadIdx.x;
    const int wid = tid >> 5;
    const int lane = tid & 31;
    const int gp = lane >> 2;   // 0..7
    const int tg = lane & 3;    // 0..3
    const int warpM = (wid & 1) * 64;
    const int warpN = (wid >> 1) * 32;
    const int bm = blockIdx.y * 128;
    const int bn = blockIdx.x * 128;

    const uint32_t sAs = (uint32_t)__cvta_generic_to_shared(As);
    const uint32_t sBs = (uint32_t)__cvta_generic_to_shared(Bs);

    // staging indices (2 x 16B chunks per thread per tile; 512 chunks per tile)
    const int arow0 = tid >> 2;             // chunk r=0: rows 0..63
    const int acv   = (tid & 3) << 2;       // k offset 0,4,8,12
    const int bkr0  = tid >> 5;             // NN: k rows 0..7 (r=0)
    const int bnv   = (tid & 31) << 2;      // NN: n offset

    float acc[4][4][4];
#pragma unroll
    for (int mi = 0; mi < 4; mi++)
#pragma unroll
        for (int ni = 0; ni < 4; ni++)
#pragma unroll
            for (int r = 0; r < 4; r++) acc[mi][ni][r] = 0.f;

    auto stage = [&](int buf, int k0) {
#pragma unroll
        for (int r = 0; r < 2; r++) {
            int row = arow0 + r * 64;
            cpasync16(sAs + (uint32_t)((buf * ASZ + row * PA + acv) * 4),
                      A + (size_t)(bm + row) * K + k0 + acv);
        }
        if (TRANSB) {
#pragma unroll
            for (int r = 0; r < 2; r++) {
                int row = arow0 + r * 64;
                cpasync16(sBs + (uint32_t)((buf * BSZ + row * PA + acv) * 4),
                          Bm + (size_t)(bn + row) * K + k0 + acv);
            }
        } else {
#pragma unroll
            for (int r = 0; r < 2; r++) {
                int kr = bkr0 + r * 8;
                cpasync16(sBs + (uint32_t)((buf * BSZ + kr * PBN + bnv) * 4),
                          Bm + (size_t)(k0 + kr) * N + bn + bnv);
            }
        }
        asm volatile("cp.async.commit_group;\n" ::);
    };

    // prologue: stage tile 0
    stage(0, 0);
    asm volatile("cp.async.wait_group 0;\n" ::);
    __syncthreads();

    const int nkt = K >> 4;
    for (int t = 0; t < nkt; t++) {
        const int buf = t & 1;
        if (t + 1 < nkt) stage(buf ^ 1, (t + 1) << 4);

        const float* Ab = As + buf * ASZ;
        const float* Bb = Bs + buf * BSZ;
#pragma unroll
        for (int ks = 0; ks < 2; ks++) {
            int kb = ks * 8;
            uint32_t af[4][4];
            uint32_t bf[4][2];
#pragma unroll
            for (int mi = 0; mi < 4; mi++) {
                int m = warpM + mi * 16 + gp;
                af[mi][0] = f2tf(Ab[m * PA + kb + tg]);
                af[mi][1] = f2tf(Ab[(m + 8) * PA + kb + tg]);
                af[mi][2] = f2tf(Ab[m * PA + kb + tg + 4]);
                af[mi][3] = f2tf(Ab[(m + 8) * PA + kb + tg + 4]);
            }
#pragma unroll
            for (int ni = 0; ni < 4; ni++) {
                int n = warpN + ni * 8 + gp;
                if (TRANSB) {
                    bf[ni][0] = f2tf(Bb[n * PA + kb + tg]);
                    bf[ni][1] = f2tf(Bb[n * PA + kb + tg + 4]);
                } else {
                    bf[ni][0] = f2tf(Bb[(kb + tg) * PBN + n]);
                    bf[ni][1] = f2tf(Bb[(kb + tg + 4) * PBN + n]);
                }
            }
#pragma unroll
            for (int mi = 0; mi < 4; mi++)
#pragma unroll
                for (int ni = 0; ni < 4; ni++)
                    mma_tf32(acc[mi][ni], af[mi], bf[ni]);
        }
        if (t + 1 < nkt) asm volatile("cp.async.wait_group 0;\n" ::);
        __syncthreads();
    }

    // ---- epilogue ----
#pragma unroll
    for (int mi = 0; mi < 4; mi++) {
        int r0 = bm + warpM + mi * 16 + gp;
        int r1 = r0 + 8;
#pragma unroll
        for (int ni = 0; ni < 4; ni++) {
            int cn = bn + warpN + ni * 8 + tg * 2;
            float2 o0, o1;
            o0.x = acc[mi][ni][0] * alpha;
            o0.y = acc[mi][ni][1] * alpha;
            o1.x = acc[mi][ni][2] * alpha;
            o1.y = acc[mi][ni][3] * alpha;
            if (bias) {
                float2 bb = *(const float2*)(bias + cn);
                o0.x += bb.x; o0.y += bb.y;
                o1.x += bb.x; o1.y += bb.y;
            }
            if (R) {
                float2 v0 = *(const float2*)(R + (size_t)r0 * N + cn);
                float2 v1 = *(const float2*)(R + (size_t)r1 * N + cn);
                o0.x += v0.x; o0.y += v0.y;
                o1.x += v1.x; o1.y += v1.y;
            }
            *(float2*)(Cm + (size_t)r0 * N + cn) = o0;
            *(float2*)(Cm + (size_t)r1 * N + cn) = o1;
        }
    }
}

// ---------------- row softmax, row length 4096 ----------------
__global__ __launch_bounds__(256) void softmax4096(float* __restrict__ S) {
    float4* p = (float4*)(S + (size_t)blockIdx.x * NTOK);
    int tid = threadIdx.x;
    float4 v[4];
    float m = -1e30f;
#pragma unroll
    for (int i = 0; i < 4; i++) {
        v[i] = p[tid + i * 256];
        m = fmaxf(m, fmaxf(fmaxf(v[i].x, v[i].y), fmaxf(v[i].z, v[i].w)));
    }
    __shared__ float red[256];
    red[tid] = m;
    __syncthreads();
    for (int s = 128; s > 0; s >>= 1) {
        if (tid < s) red[tid] = fmaxf(red[tid], red[tid + s]);
        __syncthreads();
    }
    m = red[0];
    __syncthreads();
    float sum = 0.f;
#pragma unroll
    for (int i = 0; i < 4; i++) {
        v[i].x = __expf(v[i].x - m);
        v[i].y = __expf(v[i].y - m);
        v[i].z = __expf(v[i].z - m);
        v[i].w = __expf(v[i].w - m);
        sum += v[i].x + v[i].y + v[i].z + v[i].w;
    }
    red[tid] = sum;
    __syncthreads();
    for (int s = 128; s > 0; s >>= 1) {
        if (tid < s) red[tid] += red[tid + s];
        __syncthreads();
    }
    float inv = 1.f / red[0];
#pragma unroll
    for (int i = 0; i < 4; i++) {
        v[i].x *= inv; v[i].y *= inv; v[i].z *= inv; v[i].w *= inv;
        p[tid + i * 256] = v[i];
    }
}

// ---------------- launch ----------------
extern "C" void kernel_launch(void* const* d_in, const int* in_sizes, int n_in,
                              void* d_out, int out_size) {
    const float* x     = (const float*)d_in[0];
    const float* gamma = (const float*)d_in[1];
    const float* beta  = (const float*)d_in[2];
    const float* Wq    = (const float*)d_in[3];
    const float* bq    = (const float*)d_in[4];
    const float* Wk    = (const float*)d_in[5];
    const float* bk    = (const float*)d_in[6];
    const float* Wv    = (const float*)d_in[7];
    const float* bv    = (const float*)d_in[8];
    const float* Wo    = (const float*)d_in[9];
    const float* bo    = (const float*)d_in[10];
    float* out = (float*)d_out;

    float *h, *q, *kk, *v, *o, *s, *mean, *rstd;
    cudaGetSymbolAddress((void**)&h, g_h);
    cudaGetSymbolAddress((void**)&q, g_q);
    cudaGetSymbolAddress((void**)&kk, g_k);
    cudaGetSymbolAddress((void**)&v, g_v);
    cudaGetSymbolAddress((void**)&o, g_o);
    cudaGetSymbolAddress((void**)&s, g_s);
    cudaGetSymbolAddress((void**)&mean, g_mean);
    cudaGetSymbolAddress((void**)&rstd, g_rstd);

    const size_t NC = (size_t)NTOK * CDIM;
    const size_t NN = (size_t)NTOK * NTOK;
    const int MTOT = BATCH * NTOK;                 // 16384
    const float inv_sqrt_c = 0.044194173824159216f; // 1/sqrt(512)

    // 1) GroupNorm
    gn_stats<<<BATCH * NGROUP, 512>>>(x, mean, rstd);
    gn_apply<<<(MTOT * CDIM / 4) / 256, 256>>>(x, mean, rstd, gamma, beta, h);

    // 2) Q, K, V projections: [16384,512] @ [512,512] + bias
    dim3 blk(256);
    dim3 gProj(CDIM / 128, MTOT / 128, 1);
    gemm_tf32<false><<<gProj, blk>>>(h, Wq, bq, nullptr, q, MTOT, CDIM, CDIM, 1.f, 0, 0, 0);
    gemm_tf32<false><<<gProj, blk>>>(h, Wk, bk, nullptr, kk, MTOT, CDIM, CDIM, 1.f, 0, 0, 0);
    gemm_tf32<false><<<gProj, blk>>>(h, Wv, bv, nullptr, v, MTOT, CDIM, CDIM, 1.f, 0, 0, 0);

    // 3) scores = q @ k^T * (1/sqrt(C)), batched NT
    dim3 gScore(NTOK / 128, NTOK / 128, BATCH);
    gemm_tf32<true><<<gScore, blk>>>(q, kk, nullptr, nullptr, s,
                                     NTOK, NTOK, CDIM, inv_sqrt_c, NC, NC, NN);

    // 4) softmax over each of 16384 rows
    softmax4096<<<BATCH * NTOK, 256>>>(s);

    // 5) out = attn @ v, batched NN
    dim3 gPV(CDIM / 128, NTOK / 128, BATCH);
    gemm_tf32<false><<<gPV, blk>>>(s, v, nullptr, nullptr, o,
                                   NTOK, CDIM, NTOK, 1.f, NN, NC, NC);

    // 6) final projection + bias + residual
    gemm_tf32<false><<<gProj, blk>>>(o, Wo, bo, x, out, MTOT, CDIM, CDIM, 1.f, 0, 0, 0);
}

// round 12
// speedup vs baseline: 3.6579x; 1.2856x over previous
#include <cuda_runtime.h>
#include <math.h>
#include <stdint.h>

#define BATCH 4
#define NTOK 4096      // H*W tokens
#define CDIM 512
#define NGROUP 32
#define GSZ (CDIM / NGROUP)   // 16 channels per group
#define GELEMS (NTOK * GSZ)   // 65536 elements per (b,g) group

// ---------------- scratch (static device memory; no allocations) ----------------
__device__ float g_h[(size_t)BATCH * NTOK * CDIM];
__device__ float g_q[(size_t)BATCH * NTOK * CDIM];
__device__ float g_k[(size_t)BATCH * NTOK * CDIM];
__device__ float g_v[(size_t)BATCH * NTOK * CDIM];
__device__ float g_o[(size_t)BATCH * NTOK * CDIM];
__device__ float g_s[(size_t)BATCH * NTOK * NTOK];   // 256 MB attention scores
__device__ float g_wr[4 * CDIM * CDIM];              // tf32-rounded weights
__device__ float g_mean[BATCH * NGROUP];
__device__ float g_rstd[BATCH * NGROUP];

__device__ __forceinline__ uint32_t f2tf(float f) {
    uint32_t u;
    asm("cvt.rna.tf32.f32 %0, %1;" : "=r"(u) : "f"(f));
    return u;
}
__device__ __forceinline__ float rtf(float f) { return __uint_as_float(f2tf(f)); }

// ---------------- round weight copies (one shot, 4 x 512x512) ----------------
__global__ __launch_bounds__(256) void round_w(const float* __restrict__ w0,
                                               const float* __restrict__ w1,
                                               const float* __restrict__ w2,
                                               const float* __restrict__ w3,
                                               float* __restrict__ dst) {
    const float* srcs[4] = {w0, w1, w2, w3};
    size_t i = ((size_t)blockIdx.x * 256 + threadIdx.x) * 4;
    int which = (int)(i >> 18);              // 262144 floats per matrix
    size_t off = i & ((1u << 18) - 1);
    float4 v = *(const float4*)(srcs[which] + off);
    float4 o;
    o.x = rtf(v.x); o.y = rtf(v.y); o.z = rtf(v.z); o.w = rtf(v.w);
    *(float4*)(dst + i) = o;
}

// ---------------- GroupNorm: per-(b,g) mean / rstd ----------------
__global__ __launch_bounds__(512) void gn_stats(const float* __restrict__ x,
                                                float* __restrict__ mean,
                                                float* __restrict__ rstd) {
    int bg = blockIdx.x;            // 0..127
    int b = bg >> 5, g = bg & 31;
    const float* base = x + (size_t)b * NTOK * CDIM + g * GSZ;
    float s = 0.f, ss = 0.f;
    for (int l = threadIdx.x; l < NTOK * 4; l += 512) {
        int n = l >> 2;
        int j = (l & 3) * 4;
        float4 t = *(const float4*)(base + (size_t)n * CDIM + j);
        s  += t.x + t.y + t.z + t.w;
        ss += t.x * t.x + t.y * t.y + t.z * t.z + t.w * t.w;
    }
    __shared__ float rs_[512];
    __shared__ float rss[512];
    rs_[threadIdx.x] = s;
    rss[threadIdx.x] = ss;
    __syncthreads();
    for (int st = 256; st > 0; st >>= 1) {
        if (threadIdx.x < st) {
            rs_[threadIdx.x] += rs_[threadIdx.x + st];
            rss[threadIdx.x] += rss[threadIdx.x + st];
        }
        __syncthreads();
    }
    if (threadIdx.x == 0) {
        float mu  = rs_[0] * (1.f / (float)GELEMS);
        float var = rss[0] * (1.f / (float)GELEMS) - mu * mu;
        mean[bg] = mu;
        rstd[bg] = rsqrtf(var + 1e-6f);
    }
}

// gn_apply writes tf32-rounded h (h is only consumed as a GEMM A operand)
__global__ __launch_bounds__(256) void gn_apply(const float* __restrict__ x,
                                                const float* __restrict__ mean,
                                                const float* __restrict__ rstd,
                                                const float* __restrict__ gamma,
                                                const float* __restrict__ beta,
                                                float* __restrict__ h) {
    size_t i = (size_t)blockIdx.x * blockDim.x + threadIdx.x;  // float4 index
    size_t e = i * 4;
    int c = (int)(e & (CDIM - 1));
    size_t bn = e >> 9;            // b*NTOK + n
    int b = (int)(bn >> 12);
    int g = c >> 4;
    int bg = b * NGROUP + g;
    float mu = mean[bg], rs = rstd[bg];
    float4 xv = *(const float4*)(x + e);
    float4 gv = *(const float4*)(gamma + c);
    float4 bv = *(const float4*)(beta + c);
    float4 o;
    o.x = rtf((xv.x - mu) * rs * gv.x + bv.x);
    o.y = rtf((xv.y - mu) * rs * gv.y + bv.y);
    o.z = rtf((xv.z - mu) * rs * gv.z + bv.z);
    o.w = rtf((xv.w - mu) * rs * gv.w + bv.w);
    *(float4*)(h + e) = o;
}

// ---------------- TF32 tensor-core GEMM, cp.async double-buffered ----------------
// Inputs are PRE-ROUNDED to tf32 (bit pattern), so no cvt in the hot loop.
// C[M,N] = alpha * A[M,K] @ op(B) (+ bias[N]) (+ resid[M,N]); ROUND: round C to tf32.
// Block tile 128x128, kTile 32, 256 threads = 8 warps (2 M x 4 N),
// warp tile 64x32 from m16n8k8 tf32 MMAs, fp32 accumulate. Dynamic smem.

__device__ __forceinline__ void cpasync16(uint32_t dst_smem, const float* src) {
    asm volatile("cp.async.cg.shared.global [%0], [%1], 16;\n"
                 :: "r"(dst_smem), "l"(src));
}

__device__ __forceinline__ void mma_tf32(float* c, const uint32_t* a, const uint32_t* b) {
    asm volatile(
        "mma.sync.aligned.m16n8k8.row.col.f32.tf32.tf32.f32 "
        "{%0,%1,%2,%3}, {%4,%5,%6,%7}, {%8,%9}, {%0,%1,%2,%3};\n"
        : "+f"(c[0]), "+f"(c[1]), "+f"(c[2]), "+f"(c[3])
        : "r"(a[0]), "r"(a[1]), "r"(a[2]), "r"(a[3]), "r"(b[0]), "r"(b[1]));
}

template <bool TRANSB, bool ROUND>
__global__ __launch_bounds__(256) void gemm_tf32(
    const float* __restrict__ A, const float* __restrict__ Bm,
    const float* __restrict__ bias, const float* __restrict__ resid,
    float* __restrict__ Cm, int M, int N, int K, float alpha,
    size_t sA, size_t sB, size_t sC) {
    // As[m][36]: fragment bank = (4*gp + tg) % 32 -> bijective, conflict-free.
    // TRANSB:  Bs[n][36]  (same).   !TRANSB: Bs[k][136]: bank = (8*tg + gp) % 32.
    constexpr int PA = 36;
    constexpr int PBN = 136;
    constexpr int ASZ = 128 * PA;                       // floats per buffer
    constexpr int BSZ = TRANSB ? 128 * PA : 32 * PBN;
    extern __shared__ float smem[];
    float* As = smem;                 // 2 * ASZ
    float* Bs = smem + 2 * ASZ;       // 2 * BSZ

    A  += (size_t)blockIdx.z * sA;
    Bm += (size_t)blockIdx.z * sB;
    Cm += (size_t)blockIdx.z * sC;
    const float* R = resid ? (resid + (size_t)blockIdx.z * sC) : nullptr;

    const int tid = threadIdx.x;
    const int wid = tid >> 5;
    const int lane = tid & 31;
    const int gp = lane >> 2;   // 0..7
    const int tg = lane & 3;    // 0..3
    const int warpM = (wid & 1) * 64;
    const int warpN = (wid >> 1) * 32;
    const int bm = blockIdx.y * 128;
    const int bn = blockIdx.x * 128;

    const uint32_t sAs = (uint32_t)__cvta_generic_to_shared(As);
    const uint32_t sBs = (uint32_t)__cvta_generic_to_shared(Bs);

    // staging indices: 128x32 tile = 1024 16B-chunks, 4 per thread
    const int arow = tid >> 3;             // 0..31 (+32 per r)
    const int acv  = (tid & 7) << 2;       // k offset 0..28
    const int bkr  = tid >> 5;             // NN: 0..7 (+8 per r)
    const int bnv  = (tid & 31) << 2;      // NN: n offset

    float acc[4][4][4];
#pragma unroll
    for (int mi = 0; mi < 4; mi++)
#pragma unroll
        for (int ni = 0; ni < 4; ni++)
#pragma unroll
            for (int r = 0; r < 4; r++) acc[mi][ni][r] = 0.f;

    auto stage = [&](int buf, int k0) {
#pragma unroll
        for (int r = 0; r < 4; r++) {
            int row = arow + r * 32;
            cpasync16(sAs + (uint32_t)((buf * ASZ + row * PA + acv) * 4),
                      A + (size_t)(bm + row) * K + k0 + acv);
        }
        if (TRANSB) {
#pragma unroll
            for (int r = 0; r < 4; r++) {
                int row = arow + r * 32;
                cpasync16(sBs + (uint32_t)((buf * BSZ + row * PA + acv) * 4),
                          Bm + (size_t)(bn + row) * K + k0 + acv);
            }
        } else {
#pragma unroll
            for (int r = 0; r < 4; r++) {
                int kr = bkr + r * 8;
                cpasync16(sBs + (uint32_t)((buf * BSZ + kr * PBN + bnv) * 4),
                          Bm + (size_t)(k0 + kr) * N + bn + bnv);
            }
        }
        asm volatile("cp.async.commit_group;\n" ::);
    };

    stage(0, 0);
    asm volatile("cp.async.wait_group 0;\n" ::);
    __syncthreads();

    const int nkt = K >> 5;
    for (int t = 0; t < nkt; t++) {
        const int buf = t & 1;
        if (t + 1 < nkt) stage(buf ^ 1, (t + 1) << 5);

        const uint32_t* Ab = (const uint32_t*)(As + buf * ASZ);
        const uint32_t* Bb = (const uint32_t*)(Bs + buf * BSZ);
#pragma unroll
        for (int ks = 0; ks < 4; ks++) {
            int kb = ks * 8;
            uint32_t af[4][4];
            uint32_t bf[4][2];
#pragma unroll
            for (int mi = 0; mi < 4; mi++) {
                int m = warpM + mi * 16 + gp;
                af[mi][0] = Ab[m * PA + kb + tg];
                af[mi][1] = Ab[(m + 8) * PA + kb + tg];
                af[mi][2] = Ab[m * PA + kb + tg + 4];
                af[mi][3] = Ab[(m + 8) * PA + kb + tg + 4];
            }
#pragma unroll
            for (int ni = 0; ni < 4; ni++) {
                int n = warpN + ni * 8 + gp;
                if (TRANSB) {
                    bf[ni][0] = Bb[n * PA + kb + tg];
                    bf[ni][1] = Bb[n * PA + kb + tg + 4];
                } else {
                    bf[ni][0] = Bb[(kb + tg) * PBN + n];
                    bf[ni][1] = Bb[(kb + tg + 4) * PBN + n];
                }
            }
#pragma unroll
            for (int mi = 0; mi < 4; mi++)
#pragma unroll
                for (int ni = 0; ni < 4; ni++)
                    mma_tf32(acc[mi][ni], af[mi], bf[ni]);
        }
        if (t + 1 < nkt) asm volatile("cp.async.wait_group 0;\n" ::);
        __syncthreads();
    }

    // ---- epilogue ----
#pragma unroll
    for (int mi = 0; mi < 4; mi++) {
        int r0 = bm + warpM + mi * 16 + gp;
        int r1 = r0 + 8;
#pragma unroll
        for (int ni = 0; ni < 4; ni++) {
            int cn = bn + warpN + ni * 8 + tg * 2;
            float2 o0, o1;
            o0.x = acc[mi][ni][0] * alpha;
            o0.y = acc[mi][ni][1] * alpha;
            o1.x = acc[mi][ni][2] * alpha;
            o1.y = acc[mi][ni][3] * alpha;
            if (bias) {
                float2 bb = *(const float2*)(bias + cn);
                o0.x += bb.x; o0.y += bb.y;
                o1.x += bb.x; o1.y += bb.y;
            }
            if (R) {
                float2 v0 = *(const float2*)(R + (size_t)r0 * N + cn);
                float2 v1 = *(const float2*)(R + (size_t)r1 * N + cn);
                o0.x += v0.x; o0.y += v0.y;
                o1.x += v1.x; o1.y += v1.y;
            }
            if (ROUND) {
                o0.x = rtf(o0.x); o0.y = rtf(o0.y);
                o1.x = rtf(o1.x); o1.y = rtf(o1.y);
            }
            *(float2*)(Cm + (size_t)r0 * N + cn) = o0;
            *(float2*)(Cm + (size_t)r1 * N + cn) = o1;
        }
    }
}

// ---------------- row softmax, row length 4096 (writes tf32-rounded probs) ----------------
__global__ __launch_bounds__(256) void softmax4096(float* __restrict__ S) {
    float4* p = (float4*)(S + (size_t)blockIdx.x * NTOK);
    int tid = threadIdx.x;
    float4 v[4];
    float m = -1e30f;
#pragma unroll
    for (int i = 0; i < 4; i++) {
        v[i] = p[tid + i * 256];
        m = fmaxf(m, fmaxf(fmaxf(v[i].x, v[i].y), fmaxf(v[i].z, v[i].w)));
    }
    __shared__ float red[256];
    red[tid] = m;
    __syncthreads();
    for (int s = 128; s > 0; s >>= 1) {
        if (tid < s) red[tid] = fmaxf(red[tid], red[tid + s]);
        __syncthreads();
    }
    m = red[0];
    __syncthreads();
    float sum = 0.f;
#pragma unroll
    for (int i = 0; i < 4; i++) {
        v[i].x = __expf(v[i].x - m);
        v[i].y = __expf(v[i].y - m);
        v[i].z = __expf(v[i].z - m);
        v[i].w = __expf(v[i].w - m);
        sum += v[i].x + v[i].y + v[i].z + v[i].w;
    }
    red[tid] = sum;
    __syncthreads();
    for (int s = 128; s > 0; s >>= 1) {
        if (tid < s) red[tid] += red[tid + s];
        __syncthreads();
    }
    float inv = 1.f / red[0];
#pragma unroll
    for (int i = 0; i < 4; i++) {
        v[i].x = rtf(v[i].x * inv); v[i].y = rtf(v[i].y * inv);
        v[i].z = rtf(v[i].z * inv); v[i].w = rtf(v[i].w * inv);
        p[tid + i * 256] = v[i];
    }
}

// ---------------- launch ----------------
extern "C" void kernel_launch(void* const* d_in, const int* in_sizes, int n_in,
                              void* d_out, int out_size) {
    const float* x     = (const float*)d_in[0];
    const float* gamma = (const float*)d_in[1];
    const float* beta  = (const float*)d_in[2];
    const float* Wq    = (const float*)d_in[3];
    const float* bq    = (const float*)d_in[4];
    const float* Wk    = (const float*)d_in[5];
    const float* bk    = (const float*)d_in[6];
    const float* Wv    = (const float*)d_in[7];
    const float* bv    = (const float*)d_in[8];
    const float* Wo    = (const float*)d_in[9];
    const float* bo    = (const float*)d_in[10];
    float* out = (float*)d_out;

    float *h, *q, *kk, *v, *o, *s, *wr, *mean, *rstd;
    cudaGetSymbolAddress((void**)&h, g_h);
    cudaGetSymbolAddress((void**)&q, g_q);
    cudaGetSymbolAddress((void**)&kk, g_k);
    cudaGetSymbolAddress((void**)&v, g_v);
    cudaGetSymbolAddress((void**)&o, g_o);
    cudaGetSymbolAddress((void**)&s, g_s);
    cudaGetSymbolAddress((void**)&wr, g_wr);
    cudaGetSymbolAddress((void**)&mean, g_mean);
    cudaGetSymbolAddress((void**)&rstd, g_rstd);

    const size_t NC = (size_t)NTOK * CDIM;
    const size_t NN = (size_t)NTOK * NTOK;
    const int MTOT = BATCH * NTOK;                 // 16384
    const float inv_sqrt_c = 0.044194173824159216f; // 1/sqrt(512)
    const int WSZ = CDIM * CDIM;                    // 262144

    // dynamic smem sizes (>48KB): NT 73728 B, NN 71680 B
    const int SM_NT = 2 * (128 * 36 + 128 * 36) * 4;
    const int SM_NN = 2 * (128 * 36 + 32 * 136) * 4;
    cudaFuncSetAttribute(gemm_tf32<false, true>,
                         cudaFuncAttributeMaxDynamicSharedMemorySize, SM_NN);
    cudaFuncSetAttribute(gemm_tf32<false, false>,
                         cudaFuncAttributeMaxDynamicSharedMemorySize, SM_NN);
    cudaFuncSetAttribute(gemm_tf32<true, false>,
                         cudaFuncAttributeMaxDynamicSharedMemorySize, SM_NT);

    // 0) tf32-rounded weight copies (Wq, Wk, Wv, Wo)
    round_w<<<(4 * WSZ / 4) / 256, 256>>>(Wq, Wk, Wv, Wo, wr);

    // 1) GroupNorm (h is tf32-rounded)
    gn_stats<<<BATCH * NGROUP, 512>>>(x, mean, rstd);
    gn_apply<<<(MTOT * CDIM / 4) / 256, 256>>>(x, mean, rstd, gamma, beta, h);

    // 2) Q, K, V projections: [16384,512] @ [512,512] + bias  (outputs rounded)
    dim3 blk(256);
    dim3 gProj(CDIM / 128, MTOT / 128, 1);
    gemm_tf32<false, true><<<gProj, blk, SM_NN>>>(h, wr + 0 * WSZ, bq, nullptr, q,
                                                  MTOT, CDIM, CDIM, 1.f, 0, 0, 0);
    gemm_tf32<false, true><<<gProj, blk, SM_NN>>>(h, wr + 1 * WSZ, bk, nullptr, kk,
                                                  MTOT, CDIM, CDIM, 1.f, 0, 0, 0);
    gemm_tf32<false, true><<<gProj, blk, SM_NN>>>(h, wr + 2 * WSZ, bv, nullptr, v,
                                                  MTOT, CDIM, CDIM, 1.f, 0, 0, 0);

    // 3) scores = q @ k^T * (1/sqrt(C)), batched NT (softmax rounds, no ROUND here)
    dim3 gScore(NTOK / 128, NTOK / 128, BATCH);
    gemm_tf32<true, false><<<gScore, blk, SM_NT>>>(q, kk, nullptr, nullptr, s,
                                                   NTOK, NTOK, CDIM, inv_sqrt_c, NC, NC, NN);

    // 4) softmax over each of 16384 rows (writes rounded probs)
    softmax4096<<<BATCH * NTOK, 256>>>(s);

    // 5) out = attn @ v, batched NN (output rounded; feeds final GEMM as A)
    dim3 gPV(CDIM / 128, NTOK / 128, BATCH);
    gemm_tf32<false, true><<<gPV, blk, SM_NN>>>(s, v, nullptr, nullptr, o,
                                                NTOK, CDIM, NTOK, 1.f, NN, NC, NC);

    // 6) final projection + bias + residual (full fp32 output)
    gemm_tf32<false, false><<<gProj, blk, SM_NN>>>(o, wr + 3 * WSZ, bo, x, out,
                                                   MTOT, CDIM, CDIM, 1.f, 0, 0, 0);
}

// round 14
// speedup vs baseline: 3.8760x; 1.0596x over previous
#include <cuda_runtime.h>
#include <math.h>
#include <stdint.h>

#define BATCH 4
#define NTOK 4096      // H*W tokens
#define CDIM 512
#define NGROUP 32
#define GSZ (CDIM / NGROUP)   // 16 channels per group
#define GELEMS (NTOK * GSZ)   // 65536 elements per (b,g) group

// ---------------- scratch (static device memory; no allocations) ----------------
__device__ float g_h[(size_t)BATCH * NTOK * CDIM];
__device__ float g_q[(size_t)BATCH * NTOK * CDIM];
__device__ float g_k[(size_t)BATCH * NTOK * CDIM];
__device__ float g_v[(size_t)BATCH * NTOK * CDIM];
__device__ float g_o[(size_t)BATCH * NTOK * CDIM];
__device__ float g_s[(size_t)BATCH * NTOK * NTOK];   // 256 MB attention scores
__device__ float g_wr[4 * CDIM * CDIM];              // tf32-rounded weights
__device__ float g_mean[BATCH * NGROUP];
__device__ float g_rstd[BATCH * NGROUP];

__device__ __forceinline__ uint32_t f2tf(float f) {
    uint32_t u;
    asm("cvt.rna.tf32.f32 %0, %1;" : "=r"(u) : "f"(f));
    return u;
}
__device__ __forceinline__ float rtf(float f) { return __uint_as_float(f2tf(f)); }

// ---------------- round weight copies (one shot, 4 x 512x512) ----------------
__global__ __launch_bounds__(256) void round_w(const float* __restrict__ w0,
                                               const float* __restrict__ w1,
                                               const float* __restrict__ w2,
                                               const float* __restrict__ w3,
                                               float* __restrict__ dst) {
    const float* srcs[4] = {w0, w1, w2, w3};
    size_t i = ((size_t)blockIdx.x * 256 + threadIdx.x) * 4;
    int which = (int)(i >> 18);              // 262144 floats per matrix
    size_t off = i & ((1u << 18) - 1);
    float4 v = *(const float4*)(srcs[which] + off);
    float4 o;
    o.x = rtf(v.x); o.y = rtf(v.y); o.z = rtf(v.z); o.w = rtf(v.w);
    *(float4*)(dst + i) = o;
}

// ---------------- GroupNorm: per-(b,g) mean / rstd ----------------
__global__ __launch_bounds__(512) void gn_stats(const float* __restrict__ x,
                                                float* __restrict__ mean,
                                                float* __restrict__ rstd) {
    int bg = blockIdx.x;            // 0..127
    int b = bg >> 5, g = bg & 31;
    const float* base = x + (size_t)b * NTOK * CDIM + g * GSZ;
    float s = 0.f, ss = 0.f;
    for (int l = threadIdx.x; l < NTOK * 4; l += 512) {
        int n = l >> 2;
        int j = (l & 3) * 4;
        float4 t = *(const float4*)(base + (size_t)n * CDIM + j);
        s  += t.x + t.y + t.z + t.w;
        ss += t.x * t.x + t.y * t.y + t.z * t.z + t.w * t.w;
    }
    __shared__ float rs_[512];
    __shared__ float rss[512];
    rs_[threadIdx.x] = s;
    rss[threadIdx.x] = ss;
    __syncthreads();
    for (int st = 256; st > 0; st >>= 1) {
        if (threadIdx.x < st) {
            rs_[threadIdx.x] += rs_[threadIdx.x + st];
            rss[threadIdx.x] += rss[threadIdx.x + st];
        }
        __syncthreads();
    }
    if (threadIdx.x == 0) {
        float mu  = rs_[0] * (1.f / (float)GELEMS);
        float var = rss[0] * (1.f / (float)GELEMS) - mu * mu;
        mean[bg] = mu;
        rstd[bg] = rsqrtf(var + 1e-6f);
    }
}

// gn_apply writes tf32-rounded h (h is only consumed as a GEMM A operand)
__global__ __launch_bounds__(256) void gn_apply(const float* __restrict__ x,
                                                const float* __restrict__ mean,
                                                const float* __restrict__ rstd,
                                                const float* __restrict__ gamma,
                                                const float* __restrict__ beta,
                                                float* __restrict__ h) {
    size_t i = (size_t)blockIdx.x * blockDim.x + threadIdx.x;  // float4 index
    size_t e = i * 4;
    int c = (int)(e & (CDIM - 1));
    size_t bn = e >> 9;            // b*NTOK + n
    int b = (int)(bn >> 12);
    int g = c >> 4;
    int bg = b * NGROUP + g;
    float mu = mean[bg], rs = rstd[bg];
    float4 xv = *(const float4*)(x + e);
    float4 gv = *(const float4*)(gamma + c);
    float4 bv = *(const float4*)(beta + c);
    float4 o;
    o.x = rtf((xv.x - mu) * rs * gv.x + bv.x);
    o.y = rtf((xv.y - mu) * rs * gv.y + bv.y);
    o.z = rtf((xv.z - mu) * rs * gv.z + bv.z);
    o.w = rtf((xv.w - mu) * rs * gv.w + bv.w);
    *(float4*)(h + e) = o;
}

// ---------------- TF32 tensor-core GEMM, cp.async 3-stage pipeline ----------------
// Inputs are PRE-ROUNDED to tf32 (bit pattern), so no cvt in the hot loop.
// C[M,N] = alpha * A[M,K] @ op(B) (+ bias[N]) (+ resid[M,N]); ROUND: round C to tf32.
// Block tile 128x128, kTile 32, 256 threads = 8 warps (2 M x 4 N),
// warp tile 64x32 from m16n8k8 tf32 MMAs, fp32 accumulate. Dynamic smem, 3 buffers.
// Requires K >= 64 (nkt >= 2): true for all calls here (K = 512 or 4096).

__device__ __forceinline__ void cpasync16(uint32_t dst_smem, const float* src) {
    asm volatile("cp.async.cg.shared.global [%0], [%1], 16;\n"
                 :: "r"(dst_smem), "l"(src));
}

__device__ __forceinline__ void mma_tf32(float* c, const uint32_t* a, const uint32_t* b) {
    asm volatile(
        "mma.sync.aligned.m16n8k8.row.col.f32.tf32.tf32.f32 "
        "{%0,%1,%2,%3}, {%4,%5,%6,%7}, {%8,%9}, {%0,%1,%2,%3};\n"
        : "+f"(c[0]), "+f"(c[1]), "+f"(c[2]), "+f"(c[3])
        : "r"(a[0]), "r"(a[1]), "r"(a[2]), "r"(a[3]), "r"(b[0]), "r"(b[1]));
}

template <bool TRANSB, bool ROUND>
__global__ __launch_bounds__(256) void gemm_tf32(
    const float* __restrict__ A, const float* __restrict__ Bm,
    const float* __restrict__ bias, const float* __restrict__ resid,
    float* __restrict__ Cm, int M, int N, int K, float alpha,
    size_t sA, size_t sB, size_t sC) {
    // As[m][36]: fragment bank = (4*gp + tg) % 32 -> bijective, conflict-free.
    // TRANSB:  Bs[n][36]  (same).   !TRANSB: Bs[k][136]: bank = (8*tg + gp) % 32.
    constexpr int NS = 3;
    constexpr int PA = 36;
    constexpr int PBN = 136;
    constexpr int ASZ = 128 * PA;                       // floats per buffer
    constexpr int BSZ = TRANSB ? 128 * PA : 32 * PBN;
    extern __shared__ float smem[];
    float* As = smem;                 // NS * ASZ
    float* Bs = smem + NS * ASZ;      // NS * BSZ

    A  += (size_t)blockIdx.z * sA;
    Bm += (size_t)blockIdx.z * sB;
    Cm += (size_t)blockIdx.z * sC;
    const float* R = resid ? (resid + (size_t)blockIdx.z * sC) : nullptr;

    const int tid = threadIdx.x;
    const int wid = tid >> 5;
    const int lane = tid & 31;
    const int gp = lane >> 2;   // 0..7
    const int tg = lane & 3;    // 0..3
    const int warpM = (wid & 1) * 64;
    const int warpN = (wid >> 1) * 32;
    const int bm = blockIdx.y * 128;
    const int bn = blockIdx.x * 128;

    const uint32_t sAs = (uint32_t)__cvta_generic_to_shared(As);
    const uint32_t sBs = (uint32_t)__cvta_generic_to_shared(Bs);

    // staging indices: 128x32 tile = 1024 16B-chunks, 4 per thread
    const int arow = tid >> 3;             // 0..31 (+32 per r)
    const int acv  = (tid & 7) << 2;       // k offset 0..28
    const int bkr  = tid >> 5;             // NN: 0..7 (+8 per r)
    const int bnv  = (tid & 31) << 2;      // NN: n offset

    float acc[4][4][4];
#pragma unroll
    for (int mi = 0; mi < 4; mi++)
#pragma unroll
        for (int ni = 0; ni < 4; ni++)
#pragma unroll
            for (int r = 0; r < 4; r++) acc[mi][ni][r] = 0.f;

    auto stage = [&](int buf, int k0) {
#pragma unroll
        for (int r = 0; r < 4; r++) {
            int row = arow + r * 32;
            cpasync16(sAs + (uint32_t)((buf * ASZ + row * PA + acv) * 4),
                      A + (size_t)(bm + row) * K + k0 + acv);
        }
        if (TRANSB) {
#pragma unroll
            for (int r = 0; r < 4; r++) {
                int row = arow + r * 32;
                cpasync16(sBs + (uint32_t)((buf * BSZ + row * PA + acv) * 4),
                          Bm + (size_t)(bn + row) * K + k0 + acv);
            }
        } else {
#pragma unroll
            for (int r = 0; r < 4; r++) {
                int kr = bkr + r * 8;
                cpasync16(sBs + (uint32_t)((buf * BSZ + kr * PBN + bnv) * 4),
                          Bm + (size_t)(k0 + kr) * N + bn + bnv);
            }
        }
        asm volatile("cp.async.commit_group;\n" ::);
    };

    const int nkt = K >> 5;          // always >= 2 here
    // prologue: two tiles in flight
    stage(0, 0);
    stage(1, 32);

    int buf = 0;
    for (int t = 0; t < nkt; t++) {
        // oldest outstanding group (tile t) must be complete
        if (t + 1 < nkt) {
            asm volatile("cp.async.wait_group 1;\n" ::);
        } else {
            asm volatile("cp.async.wait_group 0;\n" ::);
        }
        __syncthreads();   // tile t visible to all; all warps done with buf being overwritten
        if (t + 2 < nkt) {
            int nb = buf + 2; if (nb >= NS) nb -= NS;
            stage(nb, (t + 2) << 5);
        }

        const uint32_t* Ab = (const uint32_t*)(As + buf * ASZ);
        const uint32_t* Bb = (const uint32_t*)(Bs + buf * BSZ);
#pragma unroll
        for (int ks = 0; ks < 4; ks++) {
            int kb = ks * 8;
            uint32_t af[4][4];
            uint32_t bf[4][2];
#pragma unroll
            for (int mi = 0; mi < 4; mi++) {
                int m = warpM + mi * 16 + gp;
                af[mi][0] = Ab[m * PA + kb + tg];
                af[mi][1] = Ab[(m + 8) * PA + kb + tg];
                af[mi][2] = Ab[m * PA + kb + tg + 4];
                af[mi][3] = Ab[(m + 8) * PA + kb + tg + 4];
            }
#pragma unroll
            for (int ni = 0; ni < 4; ni++) {
                int n = warpN + ni * 8 + gp;
                if (TRANSB) {
                    bf[ni][0] = Bb[n * PA + kb + tg];
                    bf[ni][1] = Bb[n * PA + kb + tg + 4];
                } else {
                    bf[ni][0] = Bb[(kb + tg) * PBN + n];
                    bf[ni][1] = Bb[(kb + tg + 4) * PBN + n];
                }
            }
#pragma unroll
            for (int mi = 0; mi < 4; mi++)
#pragma unroll
                for (int ni = 0; ni < 4; ni++)
                    mma_tf32(acc[mi][ni], af[mi], bf[ni]);
        }
        buf++; if (buf >= NS) buf = 0;
    }

    // ---- epilogue ----
#pragma unroll
    for (int mi = 0; mi < 4; mi++) {
        int r0 = bm + warpM + mi * 16 + gp;
        int r1 = r0 + 8;
#pragma unroll
        for (int ni = 0; ni < 4; ni++) {
            int cn = bn + warpN + ni * 8 + tg * 2;
            float2 o0, o1;
            o0.x = acc[mi][ni][0] * alpha;
            o0.y = acc[mi][ni][1] * alpha;
            o1.x = acc[mi][ni][2] * alpha;
            o1.y = acc[mi][ni][3] * alpha;
            if (bias) {
                float2 bb = *(const float2*)(bias + cn);
                o0.x += bb.x; o0.y += bb.y;
                o1.x += bb.x; o1.y += bb.y;
            }
            if (R) {
                float2 v0 = *(const float2*)(R + (size_t)r0 * N + cn);
                float2 v1 = *(const float2*)(R + (size_t)r1 * N + cn);
                o0.x += v0.x; o0.y += v0.y;
                o1.x += v1.x; o1.y += v1.y;
            }
            if (ROUND) {
                o0.x = rtf(o0.x); o0.y = rtf(o0.y);
                o1.x = rtf(o1.x); o1.y = rtf(o1.y);
            }
            *(float2*)(Cm + (size_t)r0 * N + cn) = o0;
            *(float2*)(Cm + (size_t)r1 * N + cn) = o1;
        }
    }
}

// ---------------- row softmax, row length 4096 (writes tf32-rounded probs) ----------------
// warp-shuffle reductions; 2 barriers per row instead of 16
__global__ __launch_bounds__(256) void softmax4096(float* __restrict__ S) {
    float4* p = (float4*)(S + (size_t)blockIdx.x * NTOK);
    const int tid = threadIdx.x;
    const int wid = tid >> 5;
    const int lane = tid & 31;
    float4 v[4];
    float m = -1e30f;
#pragma unroll
    for (int i = 0; i < 4; i++) {
        v[i] = p[tid + i * 256];
        m = fmaxf(m, fmaxf(fmaxf(v[i].x, v[i].y), fmaxf(v[i].z, v[i].w)));
    }
    __shared__ float redm[8];
    __shared__ float reds[8];
#pragma unroll
    for (int o = 16; o > 0; o >>= 1) m = fmaxf(m, __shfl_xor_sync(0xffffffffu, m, o));
    if (lane == 0) redm[wid] = m;
    __syncthreads();
    m = redm[0];
#pragma unroll
    for (int i = 1; i < 8; i++) m = fmaxf(m, redm[i]);

    float sum = 0.f;
#pragma unroll
    for (int i = 0; i < 4; i++) {
        v[i].x = __expf(v[i].x - m);
        v[i].y = __expf(v[i].y - m);
        v[i].z = __expf(v[i].z - m);
        v[i].w = __expf(v[i].w - m);
        sum += v[i].x + v[i].y + v[i].z + v[i].w;
    }
#pragma unroll
    for (int o = 16; o > 0; o >>= 1) sum += __shfl_xor_sync(0xffffffffu, sum, o);
    if (lane == 0) reds[wid] = sum;
    __syncthreads();
    sum = reds[0];
#pragma unroll
    for (int i = 1; i < 8; i++) sum += reds[i];

    float inv = 1.f / sum;
#pragma unroll
    for (int i = 0; i < 4; i++) {
        v[i].x = rtf(v[i].x * inv); v[i].y = rtf(v[i].y * inv);
        v[i].z = rtf(v[i].z * inv); v[i].w = rtf(v[i].w * inv);
        p[tid + i * 256] = v[i];
    }
}

// ---------------- launch ----------------
extern "C" void kernel_launch(void* const* d_in, const int* in_sizes, int n_in,
                              void* d_out, int out_size) {
    const float* x     = (const float*)d_in[0];
    const float* gamma = (const float*)d_in[1];
    const float* beta  = (const float*)d_in[2];
    const float* Wq    = (const float*)d_in[3];
    const float* bq    = (const float*)d_in[4];
    const float* Wk    = (const float*)d_in[5];
    const float* bk    = (const float*)d_in[6];
    const float* Wv    = (const float*)d_in[7];
    const float* bv    = (const float*)d_in[8];
    const float* Wo    = (const float*)d_in[9];
    const float* bo    = (const float*)d_in[10];
    float* out = (float*)d_out;

    float *h, *q, *kk, *v, *o, *s, *wr, *mean, *rstd;
    cudaGetSymbolAddress((void**)&h, g_h);
    cudaGetSymbolAddress((void**)&q, g_q);
    cudaGetSymbolAddress((void**)&kk, g_k);
    cudaGetSymbolAddress((void**)&v, g_v);
    cudaGetSymbolAddress((void**)&o, g_o);
    cudaGetSymbolAddress((void**)&s, g_s);
    cudaGetSymbolAddress((void**)&wr, g_wr);
    cudaGetSymbolAddress((void**)&mean, g_mean);
    cudaGetSymbolAddress((void**)&rstd, g_rstd);

    const size_t NC = (size_t)NTOK * CDIM;
    const size_t NN = (size_t)NTOK * NTOK;
    const int MTOT = BATCH * NTOK;                 // 16384
    const float inv_sqrt_c = 0.044194173824159216f; // 1/sqrt(512)
    const int WSZ = CDIM * CDIM;                    // 262144

    // dynamic smem (3 stages): NT 110592 B, NN 107520 B -> 2 CTAs/SM
    const int SM_NT = 3 * (128 * 36 + 128 * 36) * 4;
    const int SM_NN = 3 * (128 * 36 + 32 * 136) * 4;
    cudaFuncSetAttribute(gemm_tf32<false, true>,
                         cudaFuncAttributeMaxDynamicSharedMemorySize, SM_NN);
    cudaFuncSetAttribute(gemm_tf32<false, false>,
                         cudaFuncAttributeMaxDynamicSharedMemorySize, SM_NN);
    cudaFuncSetAttribute(gemm_tf32<true, false>,
                         cudaFuncAttributeMaxDynamicSharedMemorySize, SM_NT);

    // 0) tf32-rounded weight copies (Wq, Wk, Wv, Wo)
    round_w<<<(4 * WSZ / 4) / 256, 256>>>(Wq, Wk, Wv, Wo, wr);

    // 1) GroupNorm (h is tf32-rounded)
    gn_stats<<<BATCH * NGROUP, 512>>>(x, mean, rstd);
    gn_apply<<<(MTOT * CDIM / 4) / 256, 256>>>(x, mean, rstd, gamma, beta, h);

    // 2) Q, K, V projections: [16384,512] @ [512,512] + bias  (outputs rounded)
    dim3 blk(256);
    dim3 gProj(CDIM / 128, MTOT / 128, 1);
    gemm_tf32<false, true><<<gProj, blk, SM_NN>>>(h, wr + 0 * WSZ, bq, nullptr, q,
                                                  MTOT, CDIM, CDIM, 1.f, 0, 0, 0);
    gemm_tf32<false, true><<<gProj, blk, SM_NN>>>(h, wr + 1 * WSZ, bk, nullptr, kk,
                                                  MTOT, CDIM, CDIM, 1.f, 0, 0, 0);
    gemm_tf32<false, true><<<gProj, blk, SM_NN>>>(h, wr + 2 * WSZ, bv, nullptr, v,
                                                  MTOT, CDIM, CDIM, 1.f, 0, 0, 0);

    // 3) scores = q @ k^T * (1/sqrt(C)), batched NT (softmax rounds, no ROUND here)
    dim3 gScore(NTOK / 128, NTOK / 128, BATCH);
    gemm_tf32<true, false><<<gScore, blk, SM_NT>>>(q, kk, nullptr, nullptr, s,
                                                   NTOK, NTOK, CDIM, inv_sqrt_c, NC, NC, NN);

    // 4) softmax over each of 16384 rows (writes rounded probs)
    softmax4096<<<BATCH * NTOK, 256>>>(s);

    // 5) out = attn @ v, batched NN (output rounded; feeds final GEMM as A)
    dim3 gPV(CDIM / 128, NTOK / 128, BATCH);
    gemm_tf32<false, true><<<gPV, blk, SM_NN>>>(s, v, nullptr, nullptr, o,
                                                NTOK, CDIM, NTOK, 1.f, NN, NC, NC);

    // 6) final projection + bias + residual (full fp32 output)
    gemm_tf32<false, false><<<gProj, blk, SM_NN>>>(o, wr + 3 * WSZ, bo, x, out,
                                                   MTOT, CDIM, CDIM, 1.f, 0, 0, 0);
}